// round 9
// baseline (speedup 1.0000x reference)
#include <cuda_runtime.h>
#include <cuda_bf16.h>
#include <cstdint>

// 3x3 conv (NCHW fp32, pad 1, +bias) via single-pass TF32 mma.sync GEMM.
// R9: K' = 9 taps x 128 ch = 1152 (no term splitting). 18 stages of 64 ch.
// CTA 64px x 128oc, 256 thr, 2 CTAs/SM (96KB smem). Warp tile 32x32.
// Fragments via XOR-swizzled LDS.32 (no ldmatrix for tf32).

#define ABUF   16384               // 64px x 64ch fp32
#define BBUF   32768               // 128oc x 64ch fp32
#define SMEMSZ 98304               // 2*ABUF + 2*BBUF
#define NSTR   445440              // 3480*128

__device__ __align__(16) float g_x32[14254080];   // [n][r60][w58][c128] tf32
__device__ __align__(16) float g_w32[294912];     // [ob][tap][kh][oc128][ch64] tf32

__device__ __forceinline__ uint32_t s2u(const void* p) {
    uint32_t a;
    asm("{ .reg .u64 t; cvta.to.shared.u64 t, %1; cvt.u32.u64 %0, t; }" : "=r"(a) : "l"(p));
    return a;
}
__device__ __forceinline__ void cpa16(uint32_t d, const void* s) {
    asm volatile("cp.async.cg.shared.global [%0], [%1], 16;" :: "r"(d), "l"(s) : "memory");
}
__device__ __forceinline__ float tf32r(float f) {
    float o;
    asm("cvt.rna.tf32.f32 %0, %1;" : "=f"(o) : "f"(f));
    return o;
}
__device__ __forceinline__ void mmatf(float* d, const uint32_t* a, uint32_t b0, uint32_t b1) {
    asm volatile("mma.sync.aligned.m16n8k8.row.col.f32.tf32.tf32.f32 "
        "{%0,%1,%2,%3}, {%4,%5,%6,%7}, {%8,%9}, {%0,%1,%2,%3};"
        : "+f"(d[0]), "+f"(d[1]), "+f"(d[2]), "+f"(d[3])
        : "r"(a[0]), "r"(a[1]), "r"(a[2]), "r"(a[3]), "r"(b0), "r"(b1));
}

// ---- merged prep: blocks <3480 repack x (NHWC+halo, tf32); else w ----
__global__ void prep_kernel(const float* __restrict__ x, const float* __restrict__ w) {
    if (blockIdx.x < 3480) {
        int i = blockIdx.x * 256 + threadIdx.x;       // < 890880
        int wq = i % 58;  i /= 58;
        int r  = i % 60;  i /= 60;
        int c16 = i & 7;
        int n   = i >> 3;
        const int row = r - 1, col = wq - 1;
        const bool v = (unsigned)row < 56u && (unsigned)col < 56u;
        const float* src = x + (((size_t)n * 128 + c16 * 16) * 56 + row) * 56 + col;
        float b[16];
#pragma unroll
        for (int j = 0; j < 16; ++j)
            b[j] = tf32r(v ? __ldg(src + (size_t)j * 3136) : 0.0f);
        size_t base = ((size_t)n * 3480 + r * 58 + wq) * 128 + c16 * 16;
        *(uint4*)(g_x32 + base)      = *(uint4*)b;
        *(uint4*)(g_x32 + base + 4)  = *(uint4*)(b + 4);
        *(uint4*)(g_x32 + base + 8)  = *(uint4*)(b + 8);
        *(uint4*)(g_x32 + base + 12) = *(uint4*)(b + 12);
    } else if (threadIdx.x < 128) {
        int oc = blockIdx.x - 3480, ch = threadIdx.x;
        int ob = oc >> 7, ocb = oc & 127;
        const float* src = w + ((size_t)oc * 128 + ch) * 9;
#pragma unroll
        for (int t = 0; t < 9; ++t)
            g_w32[(((size_t)(ob * 9 + t) * 2 + (ch >> 6)) * 128 + ocb) * 64 + (ch & 63)]
                = tf32r(src[t]);
    }
}

__global__ __launch_bounds__(256, 2)
void conv_mma_kernel(const float* __restrict__ bias, float* __restrict__ out) {
    extern __shared__ __align__(16) char smem[];
    const uint32_t SB = s2u(smem);       // A: 2 x ABUF, then B: 2 x BBUF

    const int tid = threadIdx.x;
    const int p0  = blockIdx.x * 64;
    const int ob  = blockIdx.y;
    const int n   = blockIdx.z;

    // staging maps
    const int ar = tid >> 2, ac = tid & 3;           // A: row 0..63, 4 chunks
    {   }
    const int pa = p0 + ar;
    const int qa = pa + 2 * (pa / 56);               // padded-frame offset
    const int br = tid >> 1, bc = tid & 1;           // B: row 0..127, 8 chunks

    // mma map: 8 warps = 2(M) x 4(N), warp tile 32x32
    const int wid = tid >> 5, l = tid & 31;
    const int m0 = (wid & 1) * 32;
    const int n0 = (wid >> 1) * 32;
    const int lr = l >> 2, lc = l & 3;

    float acc[2][4][4];
#pragma unroll
    for (int a = 0; a < 2; ++a)
#pragma unroll
        for (int b = 0; b < 4; ++b)
#pragma unroll
            for (int c = 0; c < 4; ++c) acc[a][b][c] = 0.0f;

    auto stage = [&](int s) {
        const int tap = s >> 1, kh = s & 1;
        // A tile: 64px x 64ch
        {
            const uint32_t ab = SB + (uint32_t)(s & 1) * ABUF;
            const float* src = g_x32 + (size_t)n * NSTR
                             + (size_t)(qa + (tap / 3) * 58 + (tap % 3)) * 128 + kh * 64;
#pragma unroll
            for (int i = 0; i < 4; ++i) {
                int ck = ac + 4 * i;
                cpa16(ab + (uint32_t)ar * 256 + (uint32_t)((ck ^ (ar & 15)) << 4),
                      src + ck * 4);
            }
        }
        // B tile: 128oc x 64ch
        {
            const uint32_t bb = SB + 2u * ABUF + (uint32_t)(s & 1) * BBUF;
            const float* src = g_w32
                             + (((size_t)(ob * 9 + tap) * 2 + kh) * 128 + br) * 64;
#pragma unroll
            for (int i = 0; i < 8; ++i) {
                int ck = bc + 2 * i;
                cpa16(bb + (uint32_t)br * 256 + (uint32_t)((ck ^ (br & 15)) << 4),
                      src + ck * 4);
            }
        }
        asm volatile("cp.async.commit_group;" ::: "memory");
    };

    stage(0);

#pragma unroll 1
    for (int s = 0; s < 18; ++s) {
        asm volatile("cp.async.wait_group 0;" ::: "memory");
        __syncthreads();
        if (s + 1 < 18) stage(s + 1);

        const uint32_t* sA = (const uint32_t*)(smem + (uint32_t)(s & 1) * ABUF);
        const uint32_t* sB = (const uint32_t*)(smem + 2u * ABUF + (uint32_t)(s & 1) * BBUF);
#pragma unroll
        for (int kk = 0; kk < 8; ++kk) {
            uint32_t av[2][4];
#pragma unroll
            for (int mt = 0; mt < 2; ++mt)
#pragma unroll
                for (int h = 0; h < 2; ++h) {
                    const int row = m0 + lr + mt * 16 + h * 8;
                    const int base = row * 64 + lc;
                    av[mt][h]     = sA[base + (((2 * kk)     ^ (row & 15)) << 2)];
                    av[mt][h + 2] = sA[base + (((2 * kk + 1) ^ (row & 15)) << 2)];
                }
#pragma unroll
            for (int np = 0; np < 4; ++np) {
                const int nr = n0 + lr + np * 8;
                const int nb = nr * 64 + lc;
                const uint32_t b0 = sB[nb + (((2 * kk)     ^ (nr & 15)) << 2)];
                const uint32_t b1 = sB[nb + (((2 * kk + 1) ^ (nr & 15)) << 2)];
                mmatf(acc[0][np], av[0], b0, b1);
                mmatf(acc[1][np], av[1], b0, b1);
            }
        }
    }

    // ---- epilogue: +bias, stores (exact cover) ----
    const int rbase = p0 + m0 + lr;
    const int cb = n0 + lc * 2;
#pragma unroll
    for (int mt = 0; mt < 2; ++mt)
#pragma unroll
        for (int h2 = 0; h2 < 2; ++h2) {
            const int p = rbase + mt * 16 + h2 * 8;
#pragma unroll
            for (int nt = 0; nt < 4; ++nt) {
                const int oc = ob * 128 + cb + nt * 8;
                float* op = out + ((size_t)n * 256 + oc) * 3136 + p;
                op[0]    = acc[mt][nt][h2 * 2]     + __ldg(&bias[oc]);
                op[3136] = acc[mt][nt][h2 * 2 + 1] + __ldg(&bias[oc + 1]);
            }
        }
}

extern "C" void kernel_launch(void* const* d_in, const int* in_sizes, int n_in,
                              void* d_out, int out_size)
{
    const float* x    = (const float*)d_in[0];
    const float* w    = (const float*)d_in[1];
    const float* bias = (const float*)d_in[2];
    float* out        = (float*)d_out;

    cudaFuncSetAttribute(conv_mma_kernel,
                         cudaFuncAttributeMaxDynamicSharedMemorySize, SMEMSZ);

    prep_kernel<<<3736, 256>>>(x, w);
    dim3 grid(49, 2, 32);
    conv_mma_kernel<<<grid, 256, SMEMSZ>>>(bias, out);
}

// round 10
// speedup vs baseline: 2.0134x; 2.0134x over previous
#include <cuda_runtime.h>
#include <cuda_fp16.h>
#include <cstdint>

// 3x3 conv (NCHW fp32, pad 1, +bias) via fp16 2-term split mma.sync GEMM.
// x*w ~= xh*wh + xl*wh  (xh=fp16(x), xl=fp16(x-xh), wh=fp16(w)).
// 18 stages (9 taps x {xh,xl}), K=128ch per stage as 8 k16 chunks.
// CTA 64px x 128oc, 256 thr, 2 CTAs/SM (96KB). Warp tile 32x32, ldmatrix.

#define ABUF   16384               // 64px x 128ch fp16
#define BBUF   32768               // 128oc x 128ch fp16
#define SMEMSZ 98304               // 2*ABUF + 2*BBUF
#define NSTR   445440              // 3480*128
#define HLSTR  14254080            // 32*NSTR

__device__ __align__(16) __half g_xh[28508160];   // [hl][n][r60][w58][c128]
__device__ __align__(16) __half g_wh[294912];     // [ob*9+tap][oc128][ch128]

__device__ __forceinline__ uint32_t s2u(const void* p) {
    uint32_t a;
    asm("{ .reg .u64 t; cvta.to.shared.u64 t, %1; cvt.u32.u64 %0, t; }" : "=r"(a) : "l"(p));
    return a;
}
__device__ __forceinline__ void cpa16(uint32_t d, const void* s) {
    asm volatile("cp.async.cg.shared.global [%0], [%1], 16;" :: "r"(d), "l"(s) : "memory");
}
__device__ __forceinline__ void ldm4(uint32_t* r, uint32_t a) {
    asm volatile("ldmatrix.sync.aligned.m8n8.x4.shared.b16 {%0,%1,%2,%3}, [%4];"
        : "=r"(r[0]), "=r"(r[1]), "=r"(r[2]), "=r"(r[3]) : "r"(a));
}
__device__ __forceinline__ void mmah(float* d, const uint32_t* a, uint32_t b0, uint32_t b1) {
    asm volatile("mma.sync.aligned.m16n8k16.row.col.f32.f16.f16.f32 "
        "{%0,%1,%2,%3}, {%4,%5,%6,%7}, {%8,%9}, {%0,%1,%2,%3};"
        : "+f"(d[0]), "+f"(d[1]), "+f"(d[2]), "+f"(d[3])
        : "r"(a[0]), "r"(a[1]), "r"(a[2]), "r"(a[3]), "r"(b0), "r"(b1));
}

// ---- merged prep: blocks <3480 split x (NHWC+halo); else convert w ----
__global__ void prep_kernel(const float* __restrict__ x, const float* __restrict__ w) {
    if (blockIdx.x < 3480) {
        int i = blockIdx.x * 256 + threadIdx.x;       // < 890880
        int wq = i % 58;  i /= 58;
        int r  = i % 60;  i /= 60;
        int c16 = i & 7;
        int n   = i >> 3;
        const int row = r - 1, col = wq - 1;
        const bool v = (unsigned)row < 56u && (unsigned)col < 56u;
        const float* src = x + (((size_t)n * 128 + c16 * 16) * 56 + row) * 56 + col;
        __half hb[16], lb[16];
#pragma unroll
        for (int j = 0; j < 16; ++j) {
            float f = v ? __ldg(src + (size_t)j * 3136) : 0.0f;
            hb[j] = __float2half(f);
            lb[j] = __float2half(f - __half2float(hb[j]));
        }
        size_t base = ((size_t)n * 3480 + r * 58 + wq) * 128 + c16 * 16;
        *(uint4*)(g_xh + base)             = *(uint4*)hb;
        *(uint4*)(g_xh + base + 8)         = *(uint4*)(hb + 8);
        *(uint4*)(g_xh + HLSTR + base)     = *(uint4*)lb;
        *(uint4*)(g_xh + HLSTR + base + 8) = *(uint4*)(lb + 8);
    } else if (threadIdx.x < 128) {
        int oc = blockIdx.x - 3480, ch = threadIdx.x;
        int ob = oc >> 7, ocb = oc & 127;
        const float* src = w + ((size_t)oc * 128 + ch) * 9;
#pragma unroll
        for (int t = 0; t < 9; ++t)
            g_wh[((size_t)(ob * 9 + t) * 128 + ocb) * 128 + ch] = __float2half(src[t]);
    }
}

__global__ __launch_bounds__(256, 2)
void conv_mma_kernel(const float* __restrict__ bias, float* __restrict__ out) {
    extern __shared__ __align__(16) char smem[];
    const uint32_t SB = s2u(smem);       // A rings x2 (ABUF), B rings x2 (BBUF)

    const int tid = threadIdx.x;
    const int p0  = blockIdx.x * 64;
    const int ob  = blockIdx.y;
    const int n   = blockIdx.z;

    // staging map: jj = 16B ch-chunk (0..15), tr = row group (0..15)
    const int jj = tid & 15;
    const int tr = tid >> 4;
    int q[4];
#pragma unroll
    for (int i = 0; i < 4; ++i) {
        int p = p0 + tr + 16 * i;
        q[i] = p + 2 * (p / 56);         // offset in 58-wide padded frame
    }

    // mma map: 8 warps = 2(M) x 4(N); warp tile 32x32
    const int wid = tid >> 5, l = tid & 31;
    const int m0 = (wid & 1) * 32;
    const int n0 = (wid >> 1) * 32;
    const int rA0 = m0 + (l & 15);
    const int ahx = rA0 & 7;
    const int ahi = l >> 4;
    const int rBb = (l & 7) + ((l >> 4) << 3);
    const int bhalf = (l >> 3) & 1;
    const int bhx = l & 7;

    float acc[2][4][4];
#pragma unroll
    for (int a = 0; a < 2; ++a)
#pragma unroll
        for (int b = 0; b < 4; ++b)
#pragma unroll
            for (int c = 0; c < 4; ++c) acc[a][b][c] = 0.0f;

    auto stageA = [&](int id) {          // id = 2*tap + hl
        const int hl = id & 1, t = id >> 1;
        const uint32_t ab = SB + (uint32_t)(id & 1) * ABUF;
        const __half* src = g_xh + (size_t)hl * HLSTR + (size_t)n * NSTR
                          + (size_t)((t / 3) * 58 + (t % 3)) * 128 + jj * 8;
#pragma unroll
        for (int i = 0; i < 4; ++i) {
            int r = tr + 16 * i;
            cpa16(ab + (uint32_t)r * 256 + (uint32_t)((jj ^ (r & 7)) << 4),
                  src + (size_t)q[i] * 128);
        }
    };
    auto stageB = [&](int t) {
        const uint32_t bb = SB + 2u * ABUF + (uint32_t)(t & 1) * BBUF;
        const __half* src = g_wh + (size_t)(ob * 9 + t) * 16384 + jj * 8;
#pragma unroll
        for (int i = 0; i < 8; ++i) {
            int r = tr + 16 * i;
            cpa16(bb + (uint32_t)r * 256 + (uint32_t)((jj ^ (r & 7)) << 4),
                  src + (size_t)r * 128);
        }
    };

    // prologue: stage 0 = (xh, tap0)
    stageA(0);
    stageB(0);
    asm volatile("cp.async.commit_group;" ::: "memory");

#pragma unroll 1
    for (int s = 0; s < 18; ++s) {
        asm volatile("cp.async.wait_group 0;" ::: "memory");
        __syncthreads();
        if (s + 1 < 18) {
            stageA(s + 1);
            if (((s + 1) & 1) == 0) stageB((s + 1) >> 1);
        }
        asm volatile("cp.async.commit_group;" ::: "memory");

        const uint32_t ab = SB + (uint32_t)(s & 1) * ABUF;
        const uint32_t bb = SB + 2u * ABUF + (uint32_t)((s >> 1) & 1) * BBUF;
#pragma unroll
        for (int kk = 0; kk < 8; ++kk) {
            uint32_t af[2][4];
            const uint32_t ac = (uint32_t)(((kk * 2 + ahi) ^ ahx) << 4);
            ldm4(af[0], ab + (uint32_t)rA0 * 256 + ac);
            ldm4(af[1], ab + (uint32_t)rA0 * 256 + 4096 + ac);
            const uint32_t bc = (uint32_t)(((kk * 2 + bhalf) ^ bhx) << 4);
#pragma unroll
            for (int np = 0; np < 2; ++np) {
                uint32_t bf[4];
                ldm4(bf, bb + (uint32_t)(n0 + np * 16 + rBb) * 256 + bc);
                mmah(acc[0][2 * np],     af[0], bf[0], bf[1]);
                mmah(acc[0][2 * np + 1], af[0], bf[2], bf[3]);
                mmah(acc[1][2 * np],     af[1], bf[0], bf[1]);
                mmah(acc[1][2 * np + 1], af[1], bf[2], bf[3]);
            }
        }
    }

    // ---- epilogue: +bias, stores (exact cover) ----
    const int rbase = p0 + m0 + (l >> 2);
    const int cb = n0 + (l & 3) * 2;
#pragma unroll
    for (int mt = 0; mt < 2; ++mt)
#pragma unroll
        for (int h2 = 0; h2 < 2; ++h2) {
            const int p = rbase + mt * 16 + h2 * 8;
#pragma unroll
            for (int nt = 0; nt < 4; ++nt) {
                const int oc = ob * 128 + cb + nt * 8;
                float* op = out + ((size_t)n * 256 + oc) * 3136 + p;
                op[0]    = acc[mt][nt][h2 * 2]     + __ldg(&bias[oc]);
                op[3136] = acc[mt][nt][h2 * 2 + 1] + __ldg(&bias[oc + 1]);
            }
        }
}

extern "C" void kernel_launch(void* const* d_in, const int* in_sizes, int n_in,
                              void* d_out, int out_size)
{
    const float* x    = (const float*)d_in[0];
    const float* w    = (const float*)d_in[1];
    const float* bias = (const float*)d_in[2];
    float* out        = (float*)d_out;

    cudaFuncSetAttribute(conv_mma_kernel,
                         cudaFuncAttributeMaxDynamicSharedMemorySize, SMEMSZ);

    prep_kernel<<<3736, 256>>>(x, w);
    dim3 grid(49, 2, 32);
    conv_mma_kernel<<<grid, 256, SMEMSZ>>>(bias, out);
}

// round 11
// speedup vs baseline: 2.1976x; 1.0915x over previous
#include <cuda_runtime.h>
#include <cuda_fp16.h>
#include <cstdint>

// 3x3 conv (NCHW fp32, pad 1, +bias) via fp16 2-term split mma.sync GEMM.
// R11: 4 warps/CTA, warp tile 32x64 (2Mx2N) -> LDSM redundancy A:2x B:2x,
//      regs ~140 (cap 256 @ 128thr x 2 CTA/SM). 18 stages, same pipeline.

#define ABUF   16384               // 64px x 128ch fp16
#define BBUF   32768               // 128oc x 128ch fp16
#define SMEMSZ 98304               // 2*ABUF + 2*BBUF
#define NSTR   445440              // 3480*128
#define HLSTR  14254080            // 32*NSTR

__device__ __align__(16) __half g_xh[28508160];   // [hl][n][r60][w58][c128]
__device__ __align__(16) __half g_wh[294912];     // [ob*9+tap][oc128][ch128]

__device__ __forceinline__ uint32_t s2u(const void* p) {
    uint32_t a;
    asm("{ .reg .u64 t; cvta.to.shared.u64 t, %1; cvt.u32.u64 %0, t; }" : "=r"(a) : "l"(p));
    return a;
}
__device__ __forceinline__ void cpa16(uint32_t d, const void* s) {
    asm volatile("cp.async.cg.shared.global [%0], [%1], 16;" :: "r"(d), "l"(s) : "memory");
}
__device__ __forceinline__ void ldm4(uint32_t* r, uint32_t a) {
    asm volatile("ldmatrix.sync.aligned.m8n8.x4.shared.b16 {%0,%1,%2,%3}, [%4];"
        : "=r"(r[0]), "=r"(r[1]), "=r"(r[2]), "=r"(r[3]) : "r"(a));
}
__device__ __forceinline__ void mmah(float* d, const uint32_t* a, uint32_t b0, uint32_t b1) {
    asm volatile("mma.sync.aligned.m16n8k16.row.col.f32.f16.f16.f32 "
        "{%0,%1,%2,%3}, {%4,%5,%6,%7}, {%8,%9}, {%0,%1,%2,%3};"
        : "+f"(d[0]), "+f"(d[1]), "+f"(d[2]), "+f"(d[3])
        : "r"(a[0]), "r"(a[1]), "r"(a[2]), "r"(a[3]), "r"(b0), "r"(b1));
}

// ---- merged prep: blocks <3480 split x (NHWC+halo); else convert w ----
__global__ void prep_kernel(const float* __restrict__ x, const float* __restrict__ w) {
    if (blockIdx.x < 3480) {
        int i = blockIdx.x * 256 + threadIdx.x;       // < 890880
        int wq = i % 58;  i /= 58;
        int r  = i % 60;  i /= 60;
        int c16 = i & 7;
        int n   = i >> 3;
        const int row = r - 1, col = wq - 1;
        const bool v = (unsigned)row < 56u && (unsigned)col < 56u;
        const float* src = x + (((size_t)n * 128 + c16 * 16) * 56 + row) * 56 + col;
        __half hb[16], lb[16];
#pragma unroll
        for (int j = 0; j < 16; ++j) {
            float f = v ? __ldg(src + (size_t)j * 3136) : 0.0f;
            hb[j] = __float2half(f);
            lb[j] = __float2half(f - __half2float(hb[j]));
        }
        size_t base = ((size_t)n * 3480 + r * 58 + wq) * 128 + c16 * 16;
        *(uint4*)(g_xh + base)             = *(uint4*)hb;
        *(uint4*)(g_xh + base + 8)         = *(uint4*)(hb + 8);
        *(uint4*)(g_xh + HLSTR + base)     = *(uint4*)lb;
        *(uint4*)(g_xh + HLSTR + base + 8) = *(uint4*)(lb + 8);
    } else if (threadIdx.x < 128) {
        int oc = blockIdx.x - 3480, ch = threadIdx.x;
        int ob = oc >> 7, ocb = oc & 127;
        const float* src = w + ((size_t)oc * 128 + ch) * 9;
#pragma unroll
        for (int t = 0; t < 9; ++t)
            g_wh[((size_t)(ob * 9 + t) * 128 + ocb) * 128 + ch] = __float2half(src[t]);
    }
}

__global__ __launch_bounds__(128, 2)
void conv_mma_kernel(const float* __restrict__ bias, float* __restrict__ out) {
    extern __shared__ __align__(16) char smem[];
    const uint32_t SB = s2u(smem);       // A rings x2 (ABUF), B rings x2 (BBUF)

    const int tid = threadIdx.x;
    const int p0  = blockIdx.x * 64;
    const int ob  = blockIdx.y;
    const int n   = blockIdx.z;

    // staging map: jj = 16B ch-chunk (0..15), tr = row group (0..7)
    const int jj = tid & 15;
    const int tr = tid >> 4;
    int q[8];
#pragma unroll
    for (int i = 0; i < 8; ++i) {
        int p = p0 + tr + 8 * i;
        q[i] = p + 2 * (p / 56);         // offset in 58-wide padded frame
    }

    // mma map: 4 warps = 2(M) x 2(N); warp tile 32x64
    const int wid = tid >> 5, l = tid & 31;
    const int m0 = (wid & 1) * 32;
    const int n0 = (wid >> 1) * 64;
    const int rA0 = m0 + (l & 15);
    const int ahx = rA0 & 7;
    const int ahi = l >> 4;
    const int rBb = (l & 7) + ((l >> 4) << 3);
    const int bhalf = (l >> 3) & 1;
    const int bhx = l & 7;

    float acc[2][8][4];                  // [m-tile][n8-tile][frag]
#pragma unroll
    for (int a = 0; a < 2; ++a)
#pragma unroll
        for (int b = 0; b < 8; ++b)
#pragma unroll
            for (int c = 0; c < 4; ++c) acc[a][b][c] = 0.0f;

    auto stageA = [&](int id) {          // id = 2*tap + hl
        const int hl = id & 1, t = id >> 1;
        const uint32_t ab = SB + (uint32_t)(id & 1) * ABUF;
        const __half* src = g_xh + (size_t)hl * HLSTR + (size_t)n * NSTR
                          + (size_t)((t / 3) * 58 + (t % 3)) * 128 + jj * 8;
#pragma unroll
        for (int i = 0; i < 8; ++i) {
            int r = tr + 8 * i;
            cpa16(ab + (uint32_t)r * 256 + (uint32_t)((jj ^ (r & 7)) << 4),
                  src + (size_t)q[i] * 128);
        }
    };
    auto stageB = [&](int t) {
        const uint32_t bb = SB + 2u * ABUF + (uint32_t)(t & 1) * BBUF;
        const __half* src = g_wh + (size_t)(ob * 9 + t) * 16384 + jj * 8;
#pragma unroll
        for (int i = 0; i < 16; ++i) {
            int r = tr + 8 * i;
            cpa16(bb + (uint32_t)r * 256 + (uint32_t)((jj ^ (r & 7)) << 4),
                  src + (size_t)r * 128);
        }
    };

    // prologue: stage 0 = (xh, tap0)
    stageA(0);
    stageB(0);
    asm volatile("cp.async.commit_group;" ::: "memory");

#pragma unroll 1
    for (int s = 0; s < 18; ++s) {
        asm volatile("cp.async.wait_group 0;" ::: "memory");
        __syncthreads();
        if (s + 1 < 18) {
            stageA(s + 1);
            if (((s + 1) & 1) == 0) stageB((s + 1) >> 1);
        }
        asm volatile("cp.async.commit_group;" ::: "memory");

        const uint32_t ab = SB + (uint32_t)(s & 1) * ABUF;
        const uint32_t bb = SB + 2u * ABUF + (uint32_t)((s >> 1) & 1) * BBUF;
#pragma unroll
        for (int kk = 0; kk < 8; ++kk) {
            uint32_t af[2][4];
            const uint32_t ac = (uint32_t)(((kk * 2 + ahi) ^ ahx) << 4);
            ldm4(af[0], ab + (uint32_t)rA0 * 256 + ac);
            ldm4(af[1], ab + (uint32_t)rA0 * 256 + 4096 + ac);
            const uint32_t bc = (uint32_t)(((kk * 2 + bhalf) ^ bhx) << 4);
#pragma unroll
            for (int np = 0; np < 4; ++np) {
                uint32_t bf[4];
                ldm4(bf, bb + (uint32_t)(n0 + np * 16 + rBb) * 256 + bc);
                mmah(acc[0][2 * np],     af[0], bf[0], bf[1]);
                mmah(acc[0][2 * np + 1], af[0], bf[2], bf[3]);
                mmah(acc[1][2 * np],     af[1], bf[0], bf[1]);
                mmah(acc[1][2 * np + 1], af[1], bf[2], bf[3]);
            }
        }
    }

    // ---- epilogue: +bias, stores (exact cover) ----
    const int rbase = p0 + m0 + (l >> 2);
    const int cb = n0 + (l & 3) * 2;
#pragma unroll
    for (int mt = 0; mt < 2; ++mt)
#pragma unroll
        for (int h2 = 0; h2 < 2; ++h2) {
            const int p = rbase + mt * 16 + h2 * 8;
#pragma unroll
            for (int nt = 0; nt < 8; ++nt) {
                const int oc = ob * 128 + cb + nt * 8;
                float* op = out + ((size_t)n * 256 + oc) * 3136 + p;
                op[0]    = acc[mt][nt][h2 * 2]     + __ldg(&bias[oc]);
                op[3136] = acc[mt][nt][h2 * 2 + 1] + __ldg(&bias[oc + 1]);
            }
        }
}

extern "C" void kernel_launch(void* const* d_in, const int* in_sizes, int n_in,
                              void* d_out, int out_size)
{
    const float* x    = (const float*)d_in[0];
    const float* w    = (const float*)d_in[1];
    const float* bias = (const float*)d_in[2];
    float* out        = (float*)d_out;

    cudaFuncSetAttribute(conv_mma_kernel,
                         cudaFuncAttributeMaxDynamicSharedMemorySize, SMEMSZ);

    prep_kernel<<<3736, 256>>>(x, w);
    dim3 grid(49, 2, 32);
    conv_mma_kernel<<<grid, 128, SMEMSZ>>>(bias, out);
}

// round 12
// speedup vs baseline: 3.8484x; 1.7511x over previous
#include <cuda_runtime.h>
#include <cuda_fp16.h>
#include <cstdint>

// 3x3 conv (NCHW fp32, pad 1, +bias) via SINGLE-PASS fp16 mma.sync GEMM.
// R12: no term split — fp16(x)*fp16(w) with fp32 accum. Error ~3e-4
// (statistically identical to R9's tf32: same 11-bit mantissa, RN).
// 9 stages (one per tap, K=128ch). CTA 64px x 128oc, 4 warps (32x64 tiles),
// 2 CTAs/SM, XOR-swizzled smem, double-buffered A+B rings.

#define ABUF   16384               // 64px x 128ch fp16
#define BBUF   32768               // 128oc x 128ch fp16
#define SMEMSZ 98304               // 2*ABUF + 2*BBUF
#define NSTR   445440              // 3480*128

__device__ __align__(16) __half g_xh[14254080];   // [n][r60][w58][c128]
__device__ __align__(16) __half g_wh[294912];     // [ob*9+tap][oc128][ch128]

__device__ __forceinline__ uint32_t s2u(const void* p) {
    uint32_t a;
    asm("{ .reg .u64 t; cvta.to.shared.u64 t, %1; cvt.u32.u64 %0, t; }" : "=r"(a) : "l"(p));
    return a;
}
__device__ __forceinline__ void cpa16(uint32_t d, const void* s) {
    asm volatile("cp.async.cg.shared.global [%0], [%1], 16;" :: "r"(d), "l"(s) : "memory");
}
__device__ __forceinline__ void ldm4(uint32_t* r, uint32_t a) {
    asm volatile("ldmatrix.sync.aligned.m8n8.x4.shared.b16 {%0,%1,%2,%3}, [%4];"
        : "=r"(r[0]), "=r"(r[1]), "=r"(r[2]), "=r"(r[3]) : "r"(a));
}
__device__ __forceinline__ void mmah(float* d, const uint32_t* a, uint32_t b0, uint32_t b1) {
    asm volatile("mma.sync.aligned.m16n8k16.row.col.f32.f16.f16.f32 "
        "{%0,%1,%2,%3}, {%4,%5,%6,%7}, {%8,%9}, {%0,%1,%2,%3};"
        : "+f"(d[0]), "+f"(d[1]), "+f"(d[2]), "+f"(d[3])
        : "r"(a[0]), "r"(a[1]), "r"(a[2]), "r"(a[3]), "r"(b0), "r"(b1));
}

// ---- merged prep: blocks <3480 convert x (NHWC+halo); else convert w ----
__global__ void prep_kernel(const float* __restrict__ x, const float* __restrict__ w) {
    if (blockIdx.x < 3480) {
        int i = blockIdx.x * 256 + threadIdx.x;       // < 890880
        int wq = i % 58;  i /= 58;
        int r  = i % 60;  i /= 60;
        int c16 = i & 7;
        int n   = i >> 3;
        const int row = r - 1, col = wq - 1;
        const bool v = (unsigned)row < 56u && (unsigned)col < 56u;
        const float* src = x + (((size_t)n * 128 + c16 * 16) * 56 + row) * 56 + col;
        __half hb[16];
#pragma unroll
        for (int j = 0; j < 16; ++j)
            hb[j] = __float2half(v ? __ldg(src + (size_t)j * 3136) : 0.0f);
        size_t base = ((size_t)n * 3480 + r * 58 + wq) * 128 + c16 * 16;
        *(uint4*)(g_xh + base)     = *(uint4*)hb;
        *(uint4*)(g_xh + base + 8) = *(uint4*)(hb + 8);
    } else if (threadIdx.x < 128) {
        int oc = blockIdx.x - 3480, ch = threadIdx.x;
        int ob = oc >> 7, ocb = oc & 127;
        const float* src = w + ((size_t)oc * 128 + ch) * 9;
#pragma unroll
        for (int t = 0; t < 9; ++t)
            g_wh[((size_t)(ob * 9 + t) * 128 + ocb) * 128 + ch] = __float2half(src[t]);
    }
}

__global__ __launch_bounds__(128, 2)
void conv_mma_kernel(const float* __restrict__ bias, float* __restrict__ out) {
    extern __shared__ __align__(16) char smem[];
    const uint32_t SB = s2u(smem);       // A rings x2 (ABUF), B rings x2 (BBUF)

    const int tid = threadIdx.x;
    const int p0  = blockIdx.x * 64;
    const int ob  = blockIdx.y;
    const int n   = blockIdx.z;

    // staging map: jj = 16B ch-chunk (0..15), tr = row group (0..7)
    const int jj = tid & 15;
    const int tr = tid >> 4;
    int q[8];
#pragma unroll
    for (int i = 0; i < 8; ++i) {
        int p = p0 + tr + 8 * i;
        q[i] = p + 2 * (p / 56);         // offset in 58-wide padded frame
    }

    // mma map: 4 warps = 2(M) x 2(N); warp tile 32x64
    const int wid = tid >> 5, l = tid & 31;
    const int m0 = (wid & 1) * 32;
    const int n0 = (wid >> 1) * 64;
    const int rA0 = m0 + (l & 15);
    const int ahx = rA0 & 7;
    const int ahi = l >> 4;
    const int rBb = (l & 7) + ((l >> 4) << 3);
    const int bhalf = (l >> 3) & 1;
    const int bhx = l & 7;

    float acc[2][8][4];                  // [m-tile][n8-tile][frag]
#pragma unroll
    for (int a = 0; a < 2; ++a)
#pragma unroll
        for (int b = 0; b < 8; ++b)
#pragma unroll
            for (int c = 0; c < 4; ++c) acc[a][b][c] = 0.0f;

    auto stageA = [&](int t) {
        const uint32_t ab = SB + (uint32_t)(t & 1) * ABUF;
        const __half* src = g_xh + (size_t)n * NSTR
                          + (size_t)((t / 3) * 58 + (t % 3)) * 128 + jj * 8;
#pragma unroll
        for (int i = 0; i < 8; ++i) {
            int r = tr + 8 * i;
            cpa16(ab + (uint32_t)r * 256 + (uint32_t)((jj ^ (r & 7)) << 4),
                  src + (size_t)q[i] * 128);
        }
    };
    auto stageB = [&](int t) {
        const uint32_t bb = SB + 2u * ABUF + (uint32_t)(t & 1) * BBUF;
        const __half* src = g_wh + (size_t)(ob * 9 + t) * 16384 + jj * 8;
#pragma unroll
        for (int i = 0; i < 16; ++i) {
            int r = tr + 8 * i;
            cpa16(bb + (uint32_t)r * 256 + (uint32_t)((jj ^ (r & 7)) << 4),
                  src + (size_t)r * 128);
        }
    };

    // prologue: tap 0
    stageA(0);
    stageB(0);
    asm volatile("cp.async.commit_group;" ::: "memory");

#pragma unroll 1
    for (int s = 0; s < 9; ++s) {
        asm volatile("cp.async.wait_group 0;" ::: "memory");
        __syncthreads();
        if (s + 1 < 9) {
            stageA(s + 1);
            stageB(s + 1);
        }
        asm volatile("cp.async.commit_group;" ::: "memory");

        const uint32_t ab = SB + (uint32_t)(s & 1) * ABUF;
        const uint32_t bb = SB + 2u * ABUF + (uint32_t)(s & 1) * BBUF;
#pragma unroll
        for (int kk = 0; kk < 8; ++kk) {
            uint32_t af[2][4];
            const uint32_t ac = (uint32_t)(((kk * 2 + ahi) ^ ahx) << 4);
            ldm4(af[0], ab + (uint32_t)rA0 * 256 + ac);
            ldm4(af[1], ab + (uint32_t)rA0 * 256 + 4096 + ac);
            const uint32_t bc = (uint32_t)(((kk * 2 + bhalf) ^ bhx) << 4);
#pragma unroll
            for (int np = 0; np < 4; ++np) {
                uint32_t bf[4];
                ldm4(bf, bb + (uint32_t)(n0 + np * 16 + rBb) * 256 + bc);
                mmah(acc[0][2 * np],     af[0], bf[0], bf[1]);
                mmah(acc[0][2 * np + 1], af[0], bf[2], bf[3]);
                mmah(acc[1][2 * np],     af[1], bf[0], bf[1]);
                mmah(acc[1][2 * np + 1], af[1], bf[2], bf[3]);
            }
        }
    }

    // ---- epilogue: +bias, stores (exact cover) ----
    const int rbase = p0 + m0 + (l >> 2);
    const int cb = n0 + (l & 3) * 2;
#pragma unroll
    for (int mt = 0; mt < 2; ++mt)
#pragma unroll
        for (int h2 = 0; h2 < 2; ++h2) {
            const int p = rbase + mt * 16 + h2 * 8;
#pragma unroll
            for (int nt = 0; nt < 8; ++nt) {
                const int oc = ob * 128 + cb + nt * 8;
                float* op = out + ((size_t)n * 256 + oc) * 3136 + p;
                op[0]    = acc[mt][nt][h2 * 2]     + __ldg(&bias[oc]);
                op[3136] = acc[mt][nt][h2 * 2 + 1] + __ldg(&bias[oc + 1]);
            }
        }
}

extern "C" void kernel_launch(void* const* d_in, const int* in_sizes, int n_in,
                              void* d_out, int out_size)
{
    const float* x    = (const float*)d_in[0];
    const float* w    = (const float*)d_in[1];
    const float* bias = (const float*)d_in[2];
    float* out        = (float*)d_out;

    cudaFuncSetAttribute(conv_mma_kernel,
                         cudaFuncAttributeMaxDynamicSharedMemorySize, SMEMSZ);

    prep_kernel<<<3736, 256>>>(x, w);
    dim3 grid(49, 2, 32);
    conv_mma_kernel<<<grid, 128, SMEMSZ>>>(bias, out);
}

// round 13
// speedup vs baseline: 3.9134x; 1.0169x over previous
#include <cuda_runtime.h>
#include <cuda_fp16.h>
#include <cstdint>

// 3x3 conv (NCHW fp32, pad 1, +bias) via SINGLE-PASS fp16 mma.sync GEMM.
// R13: K=64 stages (18 of them) -> 48KB smem/CTA -> 3 CTAs/SM (12 warps)
// to hide stage-boundary bubbles. CTA 64px x 128oc, 4 warps (32x64 tiles),
// XOR-swizzled 128B smem rows, double-buffered A+B rings.

#define ABUF   8192                // 64px x 64ch fp16
#define BBUF   16384               // 128oc x 64ch fp16
#define SMEMSZ 49152               // 2*ABUF + 2*BBUF
#define NSTR   445440              // 3480*128

__device__ __align__(16) __half g_xh[14254080];   // [n][r60][w58][c128]
__device__ __align__(16) __half g_wh[294912];     // [ob*9+tap][oc128][ch128]

__device__ __forceinline__ uint32_t s2u(const void* p) {
    uint32_t a;
    asm("{ .reg .u64 t; cvta.to.shared.u64 t, %1; cvt.u32.u64 %0, t; }" : "=r"(a) : "l"(p));
    return a;
}
__device__ __forceinline__ void cpa16(uint32_t d, const void* s) {
    asm volatile("cp.async.cg.shared.global [%0], [%1], 16;" :: "r"(d), "l"(s) : "memory");
}
__device__ __forceinline__ void ldm4(uint32_t* r, uint32_t a) {
    asm volatile("ldmatrix.sync.aligned.m8n8.x4.shared.b16 {%0,%1,%2,%3}, [%4];"
        : "=r"(r[0]), "=r"(r[1]), "=r"(r[2]), "=r"(r[3]) : "r"(a));
}
__device__ __forceinline__ void mmah(float* d, const uint32_t* a, uint32_t b0, uint32_t b1) {
    asm volatile("mma.sync.aligned.m16n8k16.row.col.f32.f16.f16.f32 "
        "{%0,%1,%2,%3}, {%4,%5,%6,%7}, {%8,%9}, {%0,%1,%2,%3};"
        : "+f"(d[0]), "+f"(d[1]), "+f"(d[2]), "+f"(d[3])
        : "r"(a[0]), "r"(a[1]), "r"(a[2]), "r"(a[3]), "r"(b0), "r"(b1));
}

// ---- merged prep: blocks <3480 convert x (NHWC+halo); else convert w ----
__global__ void prep_kernel(const float* __restrict__ x, const float* __restrict__ w) {
    if (blockIdx.x < 3480) {
        int i = blockIdx.x * 256 + threadIdx.x;       // < 890880
        int wq = i % 58;  i /= 58;
        int r  = i % 60;  i /= 60;
        int c16 = i & 7;
        int n   = i >> 3;
        const int row = r - 1, col = wq - 1;
        const bool v = (unsigned)row < 56u && (unsigned)col < 56u;
        const float* src = x + (((size_t)n * 128 + c16 * 16) * 56 + row) * 56 + col;
        __half hb[16];
#pragma unroll
        for (int j = 0; j < 16; ++j)
            hb[j] = __float2half(v ? __ldg(src + (size_t)j * 3136) : 0.0f);
        size_t base = ((size_t)n * 3480 + r * 58 + wq) * 128 + c16 * 16;
        *(uint4*)(g_xh + base)     = *(uint4*)hb;
        *(uint4*)(g_xh + base + 8) = *(uint4*)(hb + 8);
    } else if (threadIdx.x < 128) {
        int oc = blockIdx.x - 3480, ch = threadIdx.x;
        int ob = oc >> 7, ocb = oc & 127;
        const float* src = w + ((size_t)oc * 128 + ch) * 9;
#pragma unroll
        for (int t = 0; t < 9; ++t)
            g_wh[((size_t)(ob * 9 + t) * 128 + ocb) * 128 + ch] = __float2half(src[t]);
    }
}

__global__ __launch_bounds__(128, 3)
void conv_mma_kernel(const float* __restrict__ bias, float* __restrict__ out) {
    extern __shared__ __align__(16) char smem[];
    const uint32_t SB = s2u(smem);       // A rings x2 (ABUF), B rings x2 (BBUF)

    const int tid = threadIdx.x;
    const int p0  = blockIdx.x * 64;
    const int ob  = blockIdx.y;
    const int n   = blockIdx.z;

    // staging map: jj = 16B ch-chunk (0..7), tr = row group (0..15)
    const int jj = tid & 7;
    const int tr = tid >> 3;
    int q[4];
#pragma unroll
    for (int i = 0; i < 4; ++i) {
        int p = p0 + tr + 16 * i;
        q[i] = p + 2 * (p / 56);         // offset in 58-wide padded frame
    }

    // mma map: 4 warps = 2(M) x 2(N); warp tile 32x64
    const int wid = tid >> 5, l = tid & 31;
    const int m0 = (wid & 1) * 32;
    const int n0 = (wid >> 1) * 64;
    const int rA0 = m0 + (l & 15);
    const int ahx = rA0 & 7;
    const int ahi = l >> 4;
    const int rBb = (l & 7) + ((l >> 4) << 3);
    const int bhalf = (l >> 3) & 1;
    const int bhx = l & 7;

    float acc[2][8][4];                  // [m-tile][n8-tile][frag]
#pragma unroll
    for (int a = 0; a < 2; ++a)
#pragma unroll
        for (int b = 0; b < 8; ++b)
#pragma unroll
            for (int c = 0; c < 4; ++c) acc[a][b][c] = 0.0f;

    // stage s: tap = s>>1, ch-half = s&1 (64 ch per stage)
    auto stageA = [&](int s) {
        const int t = s >> 1, kh = s & 1;
        const uint32_t ab = SB + (uint32_t)(s & 1) * ABUF;
        const __half* src = g_xh + (size_t)n * NSTR
                          + (size_t)((t / 3) * 58 + (t % 3)) * 128 + kh * 64 + jj * 8;
#pragma unroll
        for (int i = 0; i < 4; ++i) {
            int r = tr + 16 * i;
            cpa16(ab + (uint32_t)r * 128 + (uint32_t)((jj ^ (r & 7)) << 4),
                  src + (size_t)q[i] * 128);
        }
    };
    auto stageB = [&](int s) {
        const int t = s >> 1, kh = s & 1;
        const uint32_t bb = SB + 2u * ABUF + (uint32_t)(s & 1) * BBUF;
        const __half* src = g_wh + (size_t)(ob * 9 + t) * 16384 + kh * 64 + jj * 8;
#pragma unroll
        for (int i = 0; i < 8; ++i) {
            int r = tr + 16 * i;
            cpa16(bb + (uint32_t)r * 128 + (uint32_t)((jj ^ (r & 7)) << 4),
                  src + (size_t)r * 128);
        }
    };

    // prologue: stage 0
    stageA(0);
    stageB(0);
    asm volatile("cp.async.commit_group;" ::: "memory");

#pragma unroll 1
    for (int s = 0; s < 18; ++s) {
        asm volatile("cp.async.wait_group 0;" ::: "memory");
        __syncthreads();
        if (s + 1 < 18) {
            stageA(s + 1);
            stageB(s + 1);
        }
        asm volatile("cp.async.commit_group;" ::: "memory");

        const uint32_t ab = SB + (uint32_t)(s & 1) * ABUF;
        const uint32_t bb = SB + 2u * ABUF + (uint32_t)(s & 1) * BBUF;
#pragma unroll
        for (int kk = 0; kk < 4; ++kk) {
            uint32_t af[2][4];
            const uint32_t ac = (uint32_t)(((kk * 2 + ahi) ^ ahx) << 4);
            ldm4(af[0], ab + (uint32_t)rA0 * 128 + ac);
            ldm4(af[1], ab + (uint32_t)rA0 * 128 + 2048 + ac);
            const uint32_t bc = (uint32_t)(((kk * 2 + bhalf) ^ bhx) << 4);
#pragma unroll
            for (int np = 0; np < 4; ++np) {
                uint32_t bf[4];
                ldm4(bf, bb + (uint32_t)(n0 + np * 16 + rBb) * 128 + bc);
                mmah(acc[0][2 * np],     af[0], bf[0], bf[1]);
                mmah(acc[0][2 * np + 1], af[0], bf[2], bf[3]);
                mmah(acc[1][2 * np],     af[1], bf[0], bf[1]);
                mmah(acc[1][2 * np + 1], af[1], bf[2], bf[3]);
            }
        }
    }

    // ---- epilogue: +bias, stores (exact cover) ----
    const int rbase = p0 + m0 + (l >> 2);
    const int cb = n0 + (l & 3) * 2;
#pragma unroll
    for (int mt = 0; mt < 2; ++mt)
#pragma unroll
        for (int h2 = 0; h2 < 2; ++h2) {
            const int p = rbase + mt * 16 + h2 * 8;
#pragma unroll
            for (int nt = 0; nt < 8; ++nt) {
                const int oc = ob * 128 + cb + nt * 8;
                float* op = out + ((size_t)n * 256 + oc) * 3136 + p;
                op[0]    = acc[mt][nt][h2 * 2]     + __ldg(&bias[oc]);
                op[3136] = acc[mt][nt][h2 * 2 + 1] + __ldg(&bias[oc + 1]);
            }
        }
}

extern "C" void kernel_launch(void* const* d_in, const int* in_sizes, int n_in,
                              void* d_out, int out_size)
{
    const float* x    = (const float*)d_in[0];
    const float* w    = (const float*)d_in[1];
    const float* bias = (const float*)d_in[2];
    float* out        = (float*)d_out;

    cudaFuncSetAttribute(conv_mma_kernel,
                         cudaFuncAttributeMaxDynamicSharedMemorySize, SMEMSZ);

    prep_kernel<<<3736, 256>>>(x, w);
    dim3 grid(49, 2, 32);
    conv_mma_kernel<<<grid, 128, SMEMSZ>>>(bias, out);
}